// round 2
// baseline (speedup 1.0000x reference)
#include <cuda_runtime.h>
#include <cstdint>

#define DEVINL static __device__ __forceinline__

// ---------------- problem constants ----------------
constexpr int Bb = 16, Ll = 1024, Dk = 512, Tt = 32, FT = 128;
constexpr int TM = 128, TN = 256, TK = 32;   // CTA tile, K-chunk
constexpr int KCH = Dk / TK;                 // 16
constexpr int AS_STRIDE = 36;                // floats per A smem row (pad 32->36)
constexpr int BS_STRIDE = 36;                // floats per B smem row
constexpr int A_ELEMS = TM * AS_STRIDE;      // 4608 floats
constexpr int B_ELEMS = TN * BS_STRIDE;      // 9216 floats
constexpr int SMEM_BYTES = 2 * (A_ELEMS + B_ELEMS) * 4;  // 110592 B

DEVINL uint32_t f2tf32(float f) {
    uint32_t r;
    asm("cvt.rna.tf32.f32 %0, %1;" : "=r"(r) : "f"(f));
    return r;
}

DEVINL void mma_tf32(float* d, const uint32_t* a, const uint32_t* b) {
    asm volatile(
        "mma.sync.aligned.m16n8k8.row.col.f32.tf32.tf32.f32 "
        "{%0,%1,%2,%3}, {%4,%5,%6,%7}, {%8,%9}, {%0,%1,%2,%3};"
        : "+f"(d[0]), "+f"(d[1]), "+f"(d[2]), "+f"(d[3])
        : "r"(a[0]), "r"(a[1]), "r"(a[2]), "r"(a[3]), "r"(b[0]), "r"(b[1]));
}

// ---------------- kernel ----------------
__global__ void __launch_bounds__(256, 1)
topic_layer_kernel(const float* __restrict__ emb,
                   const float* __restrict__ topic_w,
                   const float* __restrict__ topic_b,
                   const float* __restrict__ shared_w,
                   const float* __restrict__ shared_b,
                   float* __restrict__ out) {
    extern __shared__ float smem[];
    float* As = smem;                       // [2][A_ELEMS]
    float* Bs = smem + 2 * A_ELEMS;         // [2][B_ELEMS]

    const int tid = threadIdx.x;
    const int wid = tid >> 5;
    const int lid = tid & 31;
    const int warp_m = wid >> 2;            // 0..1  (64-row band)
    const int warp_n = wid & 3;             // 0..3  (64-col band)
    const int g  = lid >> 2;                // 0..7
    const int t4 = lid & 3;                 // 0..3

    const int mt = blockIdx.x;              // 0..31 topics, 32 = shared
    const int nt = blockIdx.y;              // 0..63 position tiles
    const bool is_shared = (mt == Tt);
    const float* wptr = is_shared ? shared_w : (topic_w + (size_t)mt * FT * Dk);
    const float* bptr = is_shared ? shared_b : (topic_b + (size_t)mt * FT);
    const int n0 = nt * TN;
    const int b_idx = n0 >> 10;             // L = 1024
    const int l0 = n0 & (Ll - 1);

    // accumulators: 4 M-tiles x 8 N-tiles x 4 regs = 128 floats
    float acc[4][8][4];
    #pragma unroll
    for (int mi = 0; mi < 4; ++mi)
        #pragma unroll
        for (int ni = 0; ni < 8; ++ni)
            #pragma unroll
            for (int r = 0; r < 4; ++r) acc[mi][ni][r] = 0.0f;

    // register staging for the next chunk
    float4 ar[4], br[8];

    auto ldg_chunk = [&](int c) {
        const int k0 = c * TK;
        #pragma unroll
        for (int i = 0; i < 4; ++i) {
            const int j = tid + 256 * i;          // 0..1023
            const int row = j >> 3;
            const int kq = (j & 7) << 2;
            ar[i] = *reinterpret_cast<const float4*>(wptr + (size_t)row * Dk + k0 + kq);
        }
        #pragma unroll
        for (int i = 0; i < 8; ++i) {
            const int j = tid + 256 * i;          // 0..2047
            const int row = j >> 3;
            const int kq = (j & 7) << 2;
            br[i] = *reinterpret_cast<const float4*>(emb + (size_t)(n0 + row) * Dk + k0 + kq);
        }
    };

    auto sts_chunk = [&](int buf) {
        float* ab = As + buf * A_ELEMS;
        float* bb = Bs + buf * B_ELEMS;
        #pragma unroll
        for (int i = 0; i < 4; ++i) {
            const int j = tid + 256 * i;
            const int row = j >> 3;
            const int kq = (j & 7) << 2;
            uint4 v = make_uint4(f2tf32(ar[i].x), f2tf32(ar[i].y),
                                 f2tf32(ar[i].z), f2tf32(ar[i].w));
            *reinterpret_cast<uint4*>(ab + row * AS_STRIDE + kq) = v;
        }
        #pragma unroll
        for (int i = 0; i < 8; ++i) {
            const int j = tid + 256 * i;
            const int row = j >> 3;
            const int kq = (j & 7) << 2;
            uint4 v = make_uint4(f2tf32(br[i].x), f2tf32(br[i].y),
                                 f2tf32(br[i].z), f2tf32(br[i].w));
            *reinterpret_cast<uint4*>(bb + row * BS_STRIDE + kq) = v;
        }
    };

    auto compute_chunk = [&](int buf) {
        const float* ab = As + buf * A_ELEMS;
        const float* bb = Bs + buf * B_ELEMS;
        #pragma unroll
        for (int ks = 0; ks < 4; ++ks) {
            const int k0 = ks * 8;
            uint32_t af[4][4], bf[8][2];
            #pragma unroll
            for (int mi = 0; mi < 4; ++mi) {
                const uint32_t* p = reinterpret_cast<const uint32_t*>(
                    ab + (warp_m * 64 + mi * 16 + g) * AS_STRIDE + k0 + t4);
                af[mi][0] = p[0];
                af[mi][1] = p[8 * AS_STRIDE];
                af[mi][2] = p[4];
                af[mi][3] = p[8 * AS_STRIDE + 4];
            }
            #pragma unroll
            for (int ni = 0; ni < 8; ++ni) {
                const uint32_t* q = reinterpret_cast<const uint32_t*>(
                    bb + (warp_n * 64 + ni * 8 + g) * BS_STRIDE + k0 + t4);
                bf[ni][0] = q[0];
                bf[ni][1] = q[4];
            }
            #pragma unroll
            for (int mi = 0; mi < 4; ++mi)
                #pragma unroll
                for (int ni = 0; ni < 8; ++ni)
                    mma_tf32(acc[mi][ni], af[mi], bf[ni]);
        }
    };

    // ---------------- software-pipelined mainloop ----------------
    ldg_chunk(0);
    sts_chunk(0);
    __syncthreads();

    for (int c = 0; c < KCH; ++c) {
        if (c + 1 < KCH) ldg_chunk(c + 1);     // overlap LDG with compute
        compute_chunk(c & 1);
        if (c + 1 < KCH) sts_chunk((c + 1) & 1);
        __syncthreads();
    }

    // ---------------- epilogue: bias + direct stores -------------
    if (!is_shared) {
        const size_t base = ((size_t)(mt * Bb + b_idx) * 256) * Ll + l0;
        #pragma unroll
        for (int mi = 0; mi < 4; ++mi) {
            const int m0 = warp_m * 64 + mi * 16 + g;
            const float bia0 = bptr[m0];
            const float bia1 = bptr[m0 + 8];
            #pragma unroll
            for (int ni = 0; ni < 8; ++ni) {
                const int nn = warp_n * 64 + ni * 8 + 2 * t4;
                float2 v0 = make_float2(acc[mi][ni][0] + bia0, acc[mi][ni][1] + bia0);
                float2 v1 = make_float2(acc[mi][ni][2] + bia1, acc[mi][ni][3] + bia1);
                *reinterpret_cast<float2*>(out + base + (size_t)m0 * Ll + nn) = v0;
                *reinterpret_cast<float2*>(out + base + (size_t)(m0 + 8) * Ll + nn) = v1;
            }
        }
    } else {
        #pragma unroll
        for (int mi = 0; mi < 4; ++mi) {
            const int m0 = warp_m * 64 + mi * 16 + g;
            const float bia0 = bptr[m0];
            const float bia1 = bptr[m0 + 8];
            #pragma unroll
            for (int ni = 0; ni < 8; ++ni) {
                const int nn = warp_n * 64 + ni * 8 + 2 * t4;
                float2 v0 = make_float2(acc[mi][ni][0] + bia0, acc[mi][ni][1] + bia0);
                float2 v1 = make_float2(acc[mi][ni][2] + bia1, acc[mi][ni][3] + bia1);
                for (int t = 0; t < Tt; ++t) {
                    const size_t base =
                        ((size_t)(t * Bb + b_idx) * 256 + FT) * Ll + l0;
                    *reinterpret_cast<float2*>(out + base + (size_t)m0 * Ll + nn) = v0;
                    *reinterpret_cast<float2*>(out + base + (size_t)(m0 + 8) * Ll + nn) = v1;
                }
            }
        }
    }
}

// ---------------- launch ----------------
extern "C" void kernel_launch(void* const* d_in, const int* in_sizes, int n_in,
                              void* d_out, int out_size) {
    const float* emb      = (const float*)d_in[0];
    const float* topic_w  = (const float*)d_in[1];
    const float* topic_b  = (const float*)d_in[2];
    const float* shared_w = (const float*)d_in[3];
    const float* shared_b = (const float*)d_in[4];
    float* out            = (float*)d_out;

    cudaFuncSetAttribute(topic_layer_kernel,
                         cudaFuncAttributeMaxDynamicSharedMemorySize, SMEM_BYTES);

    dim3 grid(Tt + 1, (Bb * Ll) / TN);   // (33, 64)
    topic_layer_kernel<<<grid, 256, SMEM_BYTES>>>(emb, topic_w, topic_b,
                                                  shared_w, shared_b, out);
}

// round 3
// speedup vs baseline: 1.1433x; 1.1433x over previous
#include <cuda_runtime.h>
#include <cstdint>

#define DEVINL static __device__ __forceinline__

// ---------------- problem constants ----------------
constexpr int Bb = 16, Ll = 1024, Dk = 512, Tt = 32, FT = 128;
constexpr int TM = 128, TN = 256, TK = 32;
constexpr int KCH = Dk / TK;                  // 16
constexpr int MT = 33, NT = 64;               // m-tiles (32 topics + shared), n-tiles
constexpr int A_CHUNK = 4096;                 // floats per (mt, c): 4ks*2wm*4mi*32lane*4
constexpr int B_CHUNK = 8192;                 // floats per (nt, c): 4ks*4wn*4p*32lane*4
constexpr int STAGE_FLOATS = A_CHUNK + B_CHUNK;  // 12288
constexpr int STAGES = 4;
constexpr int SMEM_BYTES = STAGES * STAGE_FLOATS * 4;  // 196608

// fragment-ordered TF32 scratch (static device arrays: allocation-legal)
__device__ float g_A[(size_t)MT * KCH * A_CHUNK];   // 8.65 MB
__device__ float g_B[(size_t)NT * KCH * B_CHUNK];   // 33.5 MB

DEVINL uint32_t f2tf32(float f) {
    uint32_t r;
    asm("cvt.rna.tf32.f32 %0, %1;" : "=r"(r) : "f"(f));
    return r;
}

DEVINL uint32_t smem_u32(const void* p) {
    uint32_t a;
    asm("{ .reg .u64 t; cvta.to.shared.u64 t, %1; cvt.u32.u64 %0, t; }"
        : "=r"(a) : "l"(p));
    return a;
}

DEVINL void cp16(uint32_t dst, const void* src) {
    asm volatile("cp.async.cg.shared.global [%0], [%1], 16;\n"
                 :: "r"(dst), "l"(src));
}

DEVINL void mma_tf32(float* d, const uint32_t* a, const uint32_t* b) {
    asm volatile(
        "mma.sync.aligned.m16n8k8.row.col.f32.tf32.tf32.f32 "
        "{%0,%1,%2,%3}, {%4,%5,%6,%7}, {%8,%9}, {%0,%1,%2,%3};"
        : "+f"(d[0]), "+f"(d[1]), "+f"(d[2]), "+f"(d[3])
        : "r"(a[0]), "r"(a[1]), "r"(a[2]), "r"(a[3]), "r"(b[0]), "r"(b[1]));
}

// ---------------- pre-pass: weights -> fragment-ordered TF32 ----------------
// inner = (((ks*2+wm)*4+mi)*32 + lane)*4 + r
//   r0=(g,t4) r1=(g+8,t4) r2=(g,t4+4) r3=(g+8,t4+4)
__global__ void prep_A(const float* __restrict__ topic_w,
                       const float* __restrict__ shared_w) {
    const int mt = blockIdx.x, c = blockIdx.y;
    const float* W = (mt == Tt) ? shared_w : (topic_w + (size_t)mt * FT * Dk);
    float* dst = g_A + (size_t)(mt * KCH + c) * A_CHUNK;
    const int tid = threadIdx.x;
    #pragma unroll
    for (int i = 0; i < 4; ++i) {
        const int chunk = tid + 256 * i;          // 0..1023
        const int lane = chunk & 31;
        const int mi = (chunk >> 5) & 3;
        const int wm = (chunk >> 7) & 1;
        const int ks = chunk >> 8;                // 0..3
        const int g = lane >> 2, t4 = lane & 3;
        const int r0 = wm * 64 + mi * 16 + g;
        const int k0 = c * 32 + ks * 8 + t4;
        uint4 u = make_uint4(f2tf32(W[(size_t)r0 * Dk + k0]),
                             f2tf32(W[(size_t)(r0 + 8) * Dk + k0]),
                             f2tf32(W[(size_t)r0 * Dk + k0 + 4]),
                             f2tf32(W[(size_t)(r0 + 8) * Dk + k0 + 4]));
        *reinterpret_cast<uint4*>(dst + (size_t)chunk * 4) = u;
    }
}

// ---------------- pre-pass: embeddings -> fragment-ordered TF32 -------------
// inner = (((ks*4+wn)*4+p)*32 + lane)*4 + q ; ni=2p+(q>>1), half=q&1
__global__ void prep_B(const float* __restrict__ emb) {
    const int nt = blockIdx.x, c = blockIdx.y;
    float* dst = g_B + (size_t)(nt * KCH + c) * B_CHUNK;
    const int tid = threadIdx.x;
    #pragma unroll
    for (int i = 0; i < 8; ++i) {
        const int chunk = tid + 256 * i;          // 0..2047
        const int lane = chunk & 31;
        const int p = (chunk >> 5) & 3;
        const int wn = (chunk >> 7) & 3;
        const int ks = chunk >> 9;                // 0..3
        const int g = lane >> 2, t4 = lane & 3;
        const int n0 = nt * 256 + wn * 64 + (2 * p) * 8 + g;
        const int k0 = c * 32 + ks * 8 + t4;
        uint4 u = make_uint4(f2tf32(emb[(size_t)n0 * Dk + k0]),
                             f2tf32(emb[(size_t)n0 * Dk + k0 + 4]),
                             f2tf32(emb[(size_t)(n0 + 8) * Dk + k0]),
                             f2tf32(emb[(size_t)(n0 + 8) * Dk + k0 + 4]));
        *reinterpret_cast<uint4*>(dst + (size_t)chunk * 4) = u;
    }
}

// ---------------- main GEMM ----------------
__global__ void __launch_bounds__(256, 1)
gemm_main(const float* __restrict__ topic_b,
          const float* __restrict__ shared_b,
          float* __restrict__ out) {
    extern __shared__ float smem[];

    const int tid = threadIdx.x;
    const int wid = tid >> 5;
    const int lid = tid & 31;
    const int warp_m = wid >> 2;            // 0..1
    const int warp_n = wid & 3;             // 0..3
    const int g = lid >> 2;
    const int t4 = lid & 3;

    const int mt = blockIdx.x;              // 0..32
    const int nt = blockIdx.y;              // 0..63
    const bool is_shared = (mt == Tt);
    const float* bptr = is_shared ? shared_b : (topic_b + (size_t)mt * FT);
    const int n0 = nt * TN;
    const int b_idx = n0 >> 10;
    const int l0 = n0 & (Ll - 1);

    float acc[4][8][4];
    #pragma unroll
    for (int mi = 0; mi < 4; ++mi)
        #pragma unroll
        for (int ni = 0; ni < 8; ++ni)
            #pragma unroll
            for (int r = 0; r < 4; ++r) acc[mi][ni][r] = 0.0f;

    const uint32_t sbase = smem_u32(smem);

    auto issue = [&](int c) {
        const int st = c & 3;
        const float* gA = g_A + (size_t)(mt * KCH + c) * A_CHUNK;
        const float* gB = g_B + (size_t)(nt * KCH + c) * B_CHUNK;
        const uint32_t sA = sbase + st * (STAGE_FLOATS * 4);
        const uint32_t sB = sA + A_CHUNK * 4;
        #pragma unroll
        for (int i = 0; i < 4; ++i)
            cp16(sA + (tid + 256 * i) * 16, gA + (size_t)(tid + 256 * i) * 4);
        #pragma unroll
        for (int i = 0; i < 8; ++i)
            cp16(sB + (tid + 256 * i) * 16, gB + (size_t)(tid + 256 * i) * 4);
    };

    issue(0); asm volatile("cp.async.commit_group;" ::: "memory");
    issue(1); asm volatile("cp.async.commit_group;" ::: "memory");
    issue(2); asm volatile("cp.async.commit_group;" ::: "memory");

    #pragma unroll 1
    for (int c = 0; c < KCH; ++c) {
        if (c < KCH - 2) asm volatile("cp.async.wait_group 2;" ::: "memory");
        else             asm volatile("cp.async.wait_group 0;" ::: "memory");
        __syncthreads();     // stage c visible to all; stage (c-1)&3 free for reuse
        if (c + 3 < KCH) {
            issue(c + 3);
            asm volatile("cp.async.commit_group;" ::: "memory");
        }

        const float* As = smem + (c & 3) * STAGE_FLOATS;
        const float* Bs = As + A_CHUNK;

        #pragma unroll
        for (int ks = 0; ks < 4; ++ks) {
            float4 af[4], bp[4];
            #pragma unroll
            for (int mi = 0; mi < 4; ++mi)
                af[mi] = *reinterpret_cast<const float4*>(
                    As + (size_t)(((ks * 2 + warp_m) * 4 + mi) * 32 + lid) * 4);
            #pragma unroll
            for (int p = 0; p < 4; ++p)
                bp[p] = *reinterpret_cast<const float4*>(
                    Bs + (size_t)(((ks * 4 + warp_n) * 4 + p) * 32 + lid) * 4);
            #pragma unroll
            for (int mi = 0; mi < 4; ++mi) {
                const uint32_t* a = reinterpret_cast<const uint32_t*>(&af[mi]);
                #pragma unroll
                for (int p = 0; p < 4; ++p) {
                    const uint32_t* b = reinterpret_cast<const uint32_t*>(&bp[p]);
                    mma_tf32(acc[mi][2 * p], a, b);
                    mma_tf32(acc[mi][2 * p + 1], a, b + 2);
                }
            }
        }
    }

    // ---------------- epilogue: bias + direct stores ----------------
    if (!is_shared) {
        const size_t base = ((size_t)(mt * Bb + b_idx) * 256) * Ll + l0;
        #pragma unroll
        for (int mi = 0; mi < 4; ++mi) {
            const int m0 = warp_m * 64 + mi * 16 + g;
            const float bia0 = bptr[m0];
            const float bia1 = bptr[m0 + 8];
            #pragma unroll
            for (int ni = 0; ni < 8; ++ni) {
                const int nn = warp_n * 64 + ni * 8 + 2 * t4;
                float2 v0 = make_float2(acc[mi][ni][0] + bia0, acc[mi][ni][1] + bia0);
                float2 v1 = make_float2(acc[mi][ni][2] + bia1, acc[mi][ni][3] + bia1);
                *reinterpret_cast<float2*>(out + base + (size_t)m0 * Ll + nn) = v0;
                *reinterpret_cast<float2*>(out + base + (size_t)(m0 + 8) * Ll + nn) = v1;
            }
        }
    } else {
        #pragma unroll
        for (int mi = 0; mi < 4; ++mi) {
            const int m0 = warp_m * 64 + mi * 16 + g;
            const float bia0 = bptr[m0];
            const float bia1 = bptr[m0 + 8];
            #pragma unroll
            for (int ni = 0; ni < 8; ++ni) {
                const int nn = warp_n * 64 + ni * 8 + 2 * t4;
                float2 v0 = make_float2(acc[mi][ni][0] + bia0, acc[mi][ni][1] + bia0);
                float2 v1 = make_float2(acc[mi][ni][2] + bia1, acc[mi][ni][3] + bia1);
                for (int t = 0; t < Tt; ++t) {
                    const size_t base =
                        ((size_t)(t * Bb + b_idx) * 256 + FT) * Ll + l0;
                    *reinterpret_cast<float2*>(out + base + (size_t)m0 * Ll + nn) = v0;
                    *reinterpret_cast<float2*>(out + base + (size_t)(m0 + 8) * Ll + nn) = v1;
                }
            }
        }
    }
}

// ---------------- launch ----------------
extern "C" void kernel_launch(void* const* d_in, const int* in_sizes, int n_in,
                              void* d_out, int out_size) {
    const float* emb      = (const float*)d_in[0];
    const float* topic_w  = (const float*)d_in[1];
    const float* topic_b  = (const float*)d_in[2];
    const float* shared_w = (const float*)d_in[3];
    const float* shared_b = (const float*)d_in[4];
    float* out            = (float*)d_out;

    cudaFuncSetAttribute(gemm_main,
                         cudaFuncAttributeMaxDynamicSharedMemorySize, SMEM_BYTES);

    prep_A<<<dim3(MT, KCH), 256>>>(topic_w, shared_w);
    prep_B<<<dim3(NT, KCH), 256>>>(emb);
    gemm_main<<<dim3(MT, NT), 256, SMEM_BYTES>>>(topic_b, shared_b, out);
}

// round 4
// speedup vs baseline: 1.3036x; 1.1401x over previous
#include <cuda_runtime.h>
#include <cstdint>

#define DEVINL static __device__ __forceinline__

// ---------------- problem constants ----------------
constexpr int Bb = 16, Ll = 1024, Dk = 512, Tt = 32, FT = 128;
constexpr int TM = 128, TN = 128, TK = 32;
constexpr int KCH = Dk / TK;                  // 16
constexpr int MT = 33, NT = 128;              // m-tiles (32 topics + shared), n-tiles
constexpr int A_CHUNK = 4096;                 // floats per (mt,c): 4ks*2wm*4mi*32lane*4
constexpr int B_CHUNK = 4096;                 // floats per (nt,c): 4ks*4wn*2p*32lane*4
constexpr int STAGE_FLOATS = A_CHUNK + B_CHUNK;  // 8192 (32 KB)
constexpr int STAGES = 3;
constexpr int SMEM_BYTES = STAGES * STAGE_FLOATS * 4;  // 98304

// fragment-ordered TF32 scratch (static device arrays: allocation-legal)
__device__ float g_A[(size_t)MT * KCH * A_CHUNK];   // 8.65 MB
__device__ float g_B[(size_t)NT * KCH * B_CHUNK];   // 33.5 MB

DEVINL uint32_t f2tf32(float f) {
    uint32_t r;
    asm("cvt.rna.tf32.f32 %0, %1;" : "=r"(r) : "f"(f));
    return r;
}

DEVINL uint32_t smem_u32(const void* p) {
    uint32_t a;
    asm("{ .reg .u64 t; cvta.to.shared.u64 t, %1; cvt.u32.u64 %0, t; }"
        : "=r"(a) : "l"(p));
    return a;
}

DEVINL void cp16(uint32_t dst, const void* src) {
    asm volatile("cp.async.cg.shared.global [%0], [%1], 16;\n"
                 :: "r"(dst), "l"(src));
}

DEVINL void mma_tf32(float* d, const uint32_t* a, const uint32_t* b) {
    asm volatile(
        "mma.sync.aligned.m16n8k8.row.col.f32.tf32.tf32.f32 "
        "{%0,%1,%2,%3}, {%4,%5,%6,%7}, {%8,%9}, {%0,%1,%2,%3};"
        : "+f"(d[0]), "+f"(d[1]), "+f"(d[2]), "+f"(d[3])
        : "r"(a[0]), "r"(a[1]), "r"(a[2]), "r"(a[3]), "r"(b[0]), "r"(b[1]));
}

// ---------------- pre-pass: weights -> fragment-ordered TF32 ----------------
// inner = (((ks*2+wm)*4+mi)*32 + lane)*4 + r
//   r0=(g,t4) r1=(g+8,t4) r2=(g,t4+4) r3=(g+8,t4+4)
__global__ void prep_A(const float* __restrict__ topic_w,
                       const float* __restrict__ shared_w) {
    const int mt = blockIdx.x, c = blockIdx.y;
    const float* W = (mt == Tt) ? shared_w : (topic_w + (size_t)mt * FT * Dk);
    float* dst = g_A + (size_t)(mt * KCH + c) * A_CHUNK;
    const int tid = threadIdx.x;
    #pragma unroll
    for (int i = 0; i < 4; ++i) {
        const int chunk = tid + 256 * i;          // 0..1023
        const int lane = chunk & 31;
        const int mi = (chunk >> 5) & 3;
        const int wm = (chunk >> 7) & 1;
        const int ks = chunk >> 8;                // 0..3
        const int g = lane >> 2, t4 = lane & 3;
        const int r0 = wm * 64 + mi * 16 + g;
        const int k0 = c * 32 + ks * 8 + t4;
        uint4 u = make_uint4(f2tf32(W[(size_t)r0 * Dk + k0]),
                             f2tf32(W[(size_t)(r0 + 8) * Dk + k0]),
                             f2tf32(W[(size_t)r0 * Dk + k0 + 4]),
                             f2tf32(W[(size_t)(r0 + 8) * Dk + k0 + 4]));
        *reinterpret_cast<uint4*>(dst + (size_t)chunk * 4) = u;
    }
}

// ---------------- pre-pass: embeddings -> fragment-ordered TF32 -------------
// inner = (((ks*4+wn)*2+p)*32 + lane)*4 + q ; ni=2p+(q>>1)
__global__ void prep_B(const float* __restrict__ emb) {
    const int nt = blockIdx.x, c = blockIdx.y;
    float* dst = g_B + (size_t)(nt * KCH + c) * B_CHUNK;
    const int tid = threadIdx.x;
    #pragma unroll
    for (int i = 0; i < 4; ++i) {
        const int chunk = tid + 256 * i;          // 0..1023
        const int lane = chunk & 31;
        const int p = (chunk >> 5) & 1;
        const int wn = (chunk >> 6) & 3;
        const int ks = chunk >> 8;                // 0..3
        const int g = lane >> 2, t4 = lane & 3;
        const int n0 = nt * TN + wn * 32 + (2 * p) * 8 + g;
        const int k0 = c * 32 + ks * 8 + t4;
        uint4 u = make_uint4(f2tf32(emb[(size_t)n0 * Dk + k0]),
                             f2tf32(emb[(size_t)n0 * Dk + k0 + 4]),
                             f2tf32(emb[(size_t)(n0 + 8) * Dk + k0]),
                             f2tf32(emb[(size_t)(n0 + 8) * Dk + k0 + 4]));
        *reinterpret_cast<uint4*>(dst + (size_t)chunk * 4) = u;
    }
}

// ---------------- main GEMM: 128x128 tile, 64x32 warp tile, 2 CTAs/SM ------
__global__ void __launch_bounds__(256, 2)
gemm_main(const float* __restrict__ topic_b,
          const float* __restrict__ shared_b,
          float* __restrict__ out) {
    extern __shared__ float smem[];

    const int tid = threadIdx.x;
    const int wid = tid >> 5;
    const int lid = tid & 31;
    const int warp_m = wid >> 2;            // 0..1
    const int warp_n = wid & 3;             // 0..3
    const int g = lid >> 2;
    const int t4 = lid & 3;

    const int mt = blockIdx.x;              // 0..32
    const int nt = blockIdx.y;              // 0..127
    const bool is_shared = (mt == Tt);
    const float* bptr = is_shared ? shared_b : (topic_b + (size_t)mt * FT);
    const int n0 = nt * TN;
    const int b_idx = n0 >> 10;
    const int l0 = n0 & (Ll - 1);

    float acc[4][4][4];                     // mi x ni x regs = 64 floats
    #pragma unroll
    for (int mi = 0; mi < 4; ++mi)
        #pragma unroll
        for (int ni = 0; ni < 4; ++ni)
            #pragma unroll
            for (int r = 0; r < 4; ++r) acc[mi][ni][r] = 0.0f;

    const uint32_t sbase = smem_u32(smem);

    auto issue = [&](int c) {
        const int st = c % STAGES;
        const float* gA = g_A + (size_t)(mt * KCH + c) * A_CHUNK;
        const float* gB = g_B + (size_t)(nt * KCH + c) * B_CHUNK;
        const uint32_t sA = sbase + st * (STAGE_FLOATS * 4);
        const uint32_t sB = sA + A_CHUNK * 4;
        #pragma unroll
        for (int i = 0; i < 4; ++i)
            cp16(sA + (tid + 256 * i) * 16, gA + (size_t)(tid + 256 * i) * 4);
        #pragma unroll
        for (int i = 0; i < 4; ++i)
            cp16(sB + (tid + 256 * i) * 16, gB + (size_t)(tid + 256 * i) * 4);
    };

    issue(0); asm volatile("cp.async.commit_group;" ::: "memory");
    issue(1); asm volatile("cp.async.commit_group;" ::: "memory");

    #pragma unroll 1
    for (int c = 0; c < KCH; ++c) {
        if (c + 1 < KCH) asm volatile("cp.async.wait_group 1;" ::: "memory");
        else             asm volatile("cp.async.wait_group 0;" ::: "memory");
        __syncthreads();     // stage c visible; stage (c-1)%3 free for refill
        if (c + 2 < KCH) {
            issue(c + 2);
            asm volatile("cp.async.commit_group;" ::: "memory");
        }

        const float* As = smem + (c % STAGES) * STAGE_FLOATS;
        const float* Bs = As + A_CHUNK;

        #pragma unroll
        for (int ks = 0; ks < 4; ++ks) {
            float4 af[4], bp[2];
            #pragma unroll
            for (int mi = 0; mi < 4; ++mi)
                af[mi] = *reinterpret_cast<const float4*>(
                    As + (size_t)(((ks * 2 + warp_m) * 4 + mi) * 32 + lid) * 4);
            #pragma unroll
            for (int p = 0; p < 2; ++p)
                bp[p] = *reinterpret_cast<const float4*>(
                    Bs + (size_t)(((ks * 4 + warp_n) * 2 + p) * 32 + lid) * 4);
            #pragma unroll
            for (int mi = 0; mi < 4; ++mi) {
                const uint32_t* a = reinterpret_cast<const uint32_t*>(&af[mi]);
                #pragma unroll
                for (int p = 0; p < 2; ++p) {
                    const uint32_t* b = reinterpret_cast<const uint32_t*>(&bp[p]);
                    mma_tf32(acc[mi][2 * p], a, b);
                    mma_tf32(acc[mi][2 * p + 1], a, b + 2);
                }
            }
        }
    }

    // ---------------- epilogue: bias + direct stores ----------------
    if (!is_shared) {
        const size_t base = ((size_t)(mt * Bb + b_idx) * 256) * Ll + l0;
        #pragma unroll
        for (int mi = 0; mi < 4; ++mi) {
            const int m0 = warp_m * 64 + mi * 16 + g;
            const float bia0 = bptr[m0];
            const float bia1 = bptr[m0 + 8];
            #pragma unroll
            for (int ni = 0; ni < 4; ++ni) {
                const int nn = warp_n * 32 + ni * 8 + 2 * t4;
                float2 v0 = make_float2(acc[mi][ni][0] + bia0, acc[mi][ni][1] + bia0);
                float2 v1 = make_float2(acc[mi][ni][2] + bia1, acc[mi][ni][3] + bia1);
                *reinterpret_cast<float2*>(out + base + (size_t)m0 * Ll + nn) = v0;
                *reinterpret_cast<float2*>(out + base + (size_t)(m0 + 8) * Ll + nn) = v1;
            }
        }
    } else {
        #pragma unroll
        for (int mi = 0; mi < 4; ++mi) {
            const int m0 = warp_m * 64 + mi * 16 + g;
            const float bia0 = bptr[m0];
            const float bia1 = bptr[m0 + 8];
            #pragma unroll
            for (int ni = 0; ni < 4; ++ni) {
                const int nn = warp_n * 32 + ni * 8 + 2 * t4;
                float2 v0 = make_float2(acc[mi][ni][0] + bia0, acc[mi][ni][1] + bia0);
                float2 v1 = make_float2(acc[mi][ni][2] + bia1, acc[mi][ni][3] + bia1);
                for (int t = 0; t < Tt; ++t) {
                    const size_t base =
                        ((size_t)(t * Bb + b_idx) * 256 + FT) * Ll + l0;
                    *reinterpret_cast<float2*>(out + base + (size_t)m0 * Ll + nn) = v0;
                    *reinterpret_cast<float2*>(out + base + (size_t)(m0 + 8) * Ll + nn) = v1;
                }
            }
        }
    }
}

// ---------------- launch ----------------
extern "C" void kernel_launch(void* const* d_in, const int* in_sizes, int n_in,
                              void* d_out, int out_size) {
    const float* emb      = (const float*)d_in[0];
    const float* topic_w  = (const float*)d_in[1];
    const float* topic_b  = (const float*)d_in[2];
    const float* shared_w = (const float*)d_in[3];
    const float* shared_b = (const float*)d_in[4];
    float* out            = (float*)d_out;

    cudaFuncSetAttribute(gemm_main,
                         cudaFuncAttributeMaxDynamicSharedMemorySize, SMEM_BYTES);

    prep_A<<<dim3(MT, KCH), 256>>>(topic_w, shared_w);
    prep_B<<<dim3(NT, KCH), 256>>>(emb);
    gemm_main<<<dim3(MT, NT), 256, SMEM_BYTES>>>(topic_b, shared_b, out);
}

// round 5
// speedup vs baseline: 1.3807x; 1.0591x over previous
#include <cuda_runtime.h>
#include <cstdint>

#define DEVINL static __device__ __forceinline__

// ---------------- problem constants ----------------
constexpr int Bb = 16, Ll = 1024, Dk = 512, Tt = 32, FT = 128;
constexpr int TM = 128, TN = 128, TK = 32;
constexpr int KCH = Dk / TK;                  // 16
constexpr int MT = 33, NT = 128;
constexpr int A_CHUNK = 4096;                 // floats per (mt,c)
constexpr int B_CHUNK = 4096;                 // floats per (nt,c)
constexpr int STAGE_FLOATS = A_CHUNK + B_CHUNK;  // 8192 (32 KB)
constexpr int STAGES = 3;
constexpr int SMEM_BYTES = STAGES * STAGE_FLOATS * 4;  // 98304

// fragment-ordered TF32 scratch (static device arrays: allocation-legal)
__device__ float g_A[(size_t)MT * KCH * A_CHUNK];   // 8.65 MB
__device__ float g_B[(size_t)NT * KCH * B_CHUNK];   // 33.5 MB

DEVINL uint32_t f2tf32(float f) {
    uint32_t r;
    asm("cvt.rna.tf32.f32 %0, %1;" : "=r"(r) : "f"(f));
    return r;
}

DEVINL uint32_t smem_u32(const void* p) {
    uint32_t a;
    asm("{ .reg .u64 t; cvta.to.shared.u64 t, %1; cvt.u32.u64 %0, t; }"
        : "=r"(a) : "l"(p));
    return a;
}

DEVINL void cp16(uint32_t dst, const void* src) {
    asm volatile("cp.async.cg.shared.global [%0], [%1], 16;\n"
                 :: "r"(dst), "l"(src));
}

DEVINL void mma_tf32(float* d, const uint32_t* a, const uint32_t* b) {
    asm volatile(
        "mma.sync.aligned.m16n8k8.row.col.f32.tf32.tf32.f32 "
        "{%0,%1,%2,%3}, {%4,%5,%6,%7}, {%8,%9}, {%0,%1,%2,%3};"
        : "+f"(d[0]), "+f"(d[1]), "+f"(d[2]), "+f"(d[3])
        : "r"(a[0]), "r"(a[1]), "r"(a[2]), "r"(a[3]), "r"(b[0]), "r"(b[1]));
}

// ---------------- pre-pass: weights -> fragment-ordered TF32 ----------------
// inner = (((ks*2+wm)*4+mi)*32 + lane)*4 + r ; r0=(g,t4) r1=(g+8,t4) r2=(g,t4+4) r3=(g+8,t4+4)
__global__ void prep_A(const float* __restrict__ topic_w,
                       const float* __restrict__ shared_w) {
    const int mt = blockIdx.x, c = blockIdx.y;
    const float* W = (mt == Tt) ? shared_w : (topic_w + (size_t)mt * FT * Dk);
    float* dst = g_A + (size_t)(mt * KCH + c) * A_CHUNK;
    const int tid = threadIdx.x;
    #pragma unroll
    for (int i = 0; i < 4; ++i) {
        const int chunk = tid + 256 * i;          // 0..1023
        const int lane = chunk & 31;
        const int mi = (chunk >> 5) & 3;
        const int wm = (chunk >> 7) & 1;
        const int ks = chunk >> 8;                // 0..3
        const int g = lane >> 2, t4 = lane & 3;
        const int r0 = wm * 64 + mi * 16 + g;
        const int k0 = c * 32 + ks * 8 + t4;
        uint4 u = make_uint4(f2tf32(W[(size_t)r0 * Dk + k0]),
                             f2tf32(W[(size_t)(r0 + 8) * Dk + k0]),
                             f2tf32(W[(size_t)r0 * Dk + k0 + 4]),
                             f2tf32(W[(size_t)(r0 + 8) * Dk + k0 + 4]));
        *reinterpret_cast<uint4*>(dst + (size_t)chunk * 4) = u;
    }
}

// ---------------- pre-pass: embeddings -> fragment-ordered TF32 -------------
// inner = (((ks*2+wn)*4+p)*32 + lane)*4 + q  (wn: 1 bit, p: 2 bits)
__global__ void prep_B(const float* __restrict__ emb) {
    const int nt = blockIdx.x, c = blockIdx.y;
    float* dst = g_B + (size_t)(nt * KCH + c) * B_CHUNK;
    const int tid = threadIdx.x;
    #pragma unroll
    for (int i = 0; i < 4; ++i) {
        const int chunk = tid + 256 * i;          // 0..1023
        const int lane = chunk & 31;
        const int p = (chunk >> 5) & 3;
        const int wn = (chunk >> 7) & 1;
        const int ks = chunk >> 8;                // 0..3
        const int g = lane >> 2, t4 = lane & 3;
        const int n0 = nt * TN + wn * 64 + (2 * p) * 8 + g;
        const int k0 = c * 32 + ks * 8 + t4;
        uint4 u = make_uint4(f2tf32(emb[(size_t)n0 * Dk + k0]),
                             f2tf32(emb[(size_t)n0 * Dk + k0 + 4]),
                             f2tf32(emb[(size_t)(n0 + 8) * Dk + k0]),
                             f2tf32(emb[(size_t)(n0 + 8) * Dk + k0 + 4]));
        *reinterpret_cast<uint4*>(dst + (size_t)chunk * 4) = u;
    }
}

// ---------------- main GEMM: 128x128 tile, 4 warps of 64x64, 2 CTAs/SM -----
__global__ void __launch_bounds__(128, 2)
gemm_main(const float* __restrict__ topic_b,
          const float* __restrict__ shared_b,
          float* __restrict__ out) {
    extern __shared__ float smem[];

    const int tid = threadIdx.x;
    const int wid = tid >> 5;
    const int lid = tid & 31;
    const int warp_m = wid >> 1;            // 0..1
    const int warp_n = wid & 1;             // 0..1
    const int g = lid >> 2;
    const int t4 = lid & 3;

    // shared-filter tiles scheduled first (they do 32x the stores)
    const int mt = (blockIdx.x == 0) ? Tt : (blockIdx.x - 1);
    const int nt = blockIdx.y;              // 0..127
    const bool is_shared = (mt == Tt);
    const float* bptr = is_shared ? shared_b : (topic_b + (size_t)mt * FT);
    const int n0 = nt * TN;
    const int b_idx = n0 >> 10;
    const int l0 = n0 & (Ll - 1);

    float acc[4][8][4];                     // mi x ni x regs = 128 floats
    #pragma unroll
    for (int mi = 0; mi < 4; ++mi)
        #pragma unroll
        for (int ni = 0; ni < 8; ++ni)
            #pragma unroll
            for (int r = 0; r < 4; ++r) acc[mi][ni][r] = 0.0f;

    const uint32_t sbase = smem_u32(smem);

    auto issue = [&](int c) {
        const int st = c % STAGES;
        const float* gA = g_A + (size_t)(mt * KCH + c) * A_CHUNK;
        const float* gB = g_B + (size_t)(nt * KCH + c) * B_CHUNK;
        const uint32_t sA = sbase + st * (STAGE_FLOATS * 4);
        const uint32_t sB = sA + A_CHUNK * 4;
        #pragma unroll
        for (int i = 0; i < 8; ++i)
            cp16(sA + (tid + 128 * i) * 16, gA + (size_t)(tid + 128 * i) * 4);
        #pragma unroll
        for (int i = 0; i < 8; ++i)
            cp16(sB + (tid + 128 * i) * 16, gB + (size_t)(tid + 128 * i) * 4);
    };

    issue(0); asm volatile("cp.async.commit_group;" ::: "memory");
    issue(1); asm volatile("cp.async.commit_group;" ::: "memory");

    #pragma unroll 1
    for (int c = 0; c < KCH; ++c) {
        if (c + 1 < KCH) asm volatile("cp.async.wait_group 1;" ::: "memory");
        else             asm volatile("cp.async.wait_group 0;" ::: "memory");
        __syncthreads();     // stage c visible; stage (c-1)%3 free for refill
        if (c + 2 < KCH) {
            issue(c + 2);
            asm volatile("cp.async.commit_group;" ::: "memory");
        }

        const float* As = smem + (c % STAGES) * STAGE_FLOATS;
        const float* Bs = As + A_CHUNK;

        #pragma unroll
        for (int ks = 0; ks < 4; ++ks) {
            float4 af[4], bp[4];
            #pragma unroll
            for (int mi = 0; mi < 4; ++mi)
                af[mi] = *reinterpret_cast<const float4*>(
                    As + (size_t)(((ks * 2 + warp_m) * 4 + mi) * 32 + lid) * 4);
            #pragma unroll
            for (int p = 0; p < 4; ++p)
                bp[p] = *reinterpret_cast<const float4*>(
                    Bs + (size_t)(((ks * 2 + warp_n) * 4 + p) * 32 + lid) * 4);
            #pragma unroll
            for (int mi = 0; mi < 4; ++mi) {
                const uint32_t* a = reinterpret_cast<const uint32_t*>(&af[mi]);
                #pragma unroll
                for (int p = 0; p < 4; ++p) {
                    const uint32_t* b = reinterpret_cast<const uint32_t*>(&bp[p]);
                    mma_tf32(acc[mi][2 * p], a, b);
                    mma_tf32(acc[mi][2 * p + 1], a, b + 2);
                }
            }
        }
    }

    // ---------------- epilogue: bias + direct stores ----------------
    if (!is_shared) {
        const size_t base = ((size_t)(mt * Bb + b_idx) * 256) * Ll + l0;
        #pragma unroll
        for (int mi = 0; mi < 4; ++mi) {
            const int m0 = warp_m * 64 + mi * 16 + g;
            const float bia0 = bptr[m0];
            const float bia1 = bptr[m0 + 8];
            #pragma unroll
            for (int ni = 0; ni < 8; ++ni) {
                const int nn = warp_n * 64 + ni * 8 + 2 * t4;
                float2 v0 = make_float2(acc[mi][ni][0] + bia0, acc[mi][ni][1] + bia0);
                float2 v1 = make_float2(acc[mi][ni][2] + bia1, acc[mi][ni][3] + bia1);
                *reinterpret_cast<float2*>(out + base + (size_t)m0 * Ll + nn) = v0;
                *reinterpret_cast<float2*>(out + base + (size_t)(m0 + 8) * Ll + nn) = v1;
            }
        }
    } else {
        #pragma unroll
        for (int mi = 0; mi < 4; ++mi) {
            const int m0 = warp_m * 64 + mi * 16 + g;
            const float bia0 = bptr[m0];
            const float bia1 = bptr[m0 + 8];
            #pragma unroll
            for (int ni = 0; ni < 8; ++ni) {
                const int nn = warp_n * 64 + ni * 8 + 2 * t4;
                float2 v0 = make_float2(acc[mi][ni][0] + bia0, acc[mi][ni][1] + bia0);
                float2 v1 = make_float2(acc[mi][ni][2] + bia1, acc[mi][ni][3] + bia1);
                for (int t = 0; t < Tt; ++t) {
                    const size_t base =
                        ((size_t)(t * Bb + b_idx) * 256 + FT) * Ll + l0;
                    *reinterpret_cast<float2*>(out + base + (size_t)m0 * Ll + nn) = v0;
                    *reinterpret_cast<float2*>(out + base + (size_t)(m0 + 8) * Ll + nn) = v1;
                }
            }
        }
    }
}

// ---------------- launch ----------------
extern "C" void kernel_launch(void* const* d_in, const int* in_sizes, int n_in,
                              void* d_out, int out_size) {
    const float* emb      = (const float*)d_in[0];
    const float* topic_w  = (const float*)d_in[1];
    const float* topic_b  = (const float*)d_in[2];
    const float* shared_w = (const float*)d_in[3];
    const float* shared_b = (const float*)d_in[4];
    float* out            = (float*)d_out;

    cudaFuncSetAttribute(gemm_main,
                         cudaFuncAttributeMaxDynamicSharedMemorySize, SMEM_BYTES);

    prep_A<<<dim3(MT, KCH), 256>>>(topic_w, shared_w);
    prep_B<<<dim3(NT, KCH), 256>>>(emb);
    gemm_main<<<dim3(MT, NT), 128, SMEM_BYTES>>>(topic_b, shared_b, out);
}

// round 6
// speedup vs baseline: 1.4567x; 1.0551x over previous
#include <cuda_runtime.h>
#include <cstdint>

#define DEVINL static __device__ __forceinline__

// ---------------- problem constants ----------------
constexpr int Bb = 16, Ll = 1024, Dk = 512, Tt = 32, FT = 128;
constexpr int TM = 128, TN = 128, TK = 32;
constexpr int KCH = Dk / TK;                  // 16
constexpr int MT = 33, NT = 128;
constexpr int A_CHUNK = 4096;                 // floats per (mt,c)
constexpr int B_CHUNK = 4096;                 // floats per (nt,c)
constexpr int NSTEP = KCH * 4;                // 64 K-steps of 8

// fragment-ordered TF32 scratch (+1 chunk pad so tail prefetch stays in-bounds)
__device__ float g_A[(size_t)(MT * KCH + 1) * A_CHUNK];   // ~8.7 MB
__device__ float g_B[(size_t)(NT * KCH + 1) * B_CHUNK];   // ~33.6 MB

DEVINL uint32_t f2tf32(float f) {
    uint32_t r;
    asm("cvt.rna.tf32.f32 %0, %1;" : "=r"(r) : "f"(f));
    return r;
}

DEVINL void mma_tf32(float* d, const uint32_t* a, const uint32_t* b) {
    asm volatile(
        "mma.sync.aligned.m16n8k8.row.col.f32.tf32.tf32.f32 "
        "{%0,%1,%2,%3}, {%4,%5,%6,%7}, {%8,%9}, {%0,%1,%2,%3};"
        : "+f"(d[0]), "+f"(d[1]), "+f"(d[2]), "+f"(d[3])
        : "r"(a[0]), "r"(a[1]), "r"(a[2]), "r"(a[3]), "r"(b[0]), "r"(b[1]));
}

// ---------------- pre-pass: weights -> fragment-ordered TF32 ----------------
// inner = (((ks*2+wm)*4+mi)*32 + lane)*4 + r ; r0=(g,t4) r1=(g+8,t4) r2=(g,t4+4) r3=(g+8,t4+4)
__global__ void prep_A(const float* __restrict__ topic_w,
                       const float* __restrict__ shared_w) {
    const int mt = blockIdx.x, c = blockIdx.y;
    const float* W = (mt == Tt) ? shared_w : (topic_w + (size_t)mt * FT * Dk);
    float* dst = g_A + (size_t)(mt * KCH + c) * A_CHUNK;
    const int tid = threadIdx.x;
    #pragma unroll
    for (int i = 0; i < 4; ++i) {
        const int chunk = tid + 256 * i;          // 0..1023
        const int lane = chunk & 31;
        const int mi = (chunk >> 5) & 3;
        const int wm = (chunk >> 7) & 1;
        const int ks = chunk >> 8;                // 0..3
        const int g = lane >> 2, t4 = lane & 3;
        const int r0 = wm * 64 + mi * 16 + g;
        const int k0 = c * 32 + ks * 8 + t4;
        uint4 u = make_uint4(f2tf32(W[(size_t)r0 * Dk + k0]),
                             f2tf32(W[(size_t)(r0 + 8) * Dk + k0]),
                             f2tf32(W[(size_t)r0 * Dk + k0 + 4]),
                             f2tf32(W[(size_t)(r0 + 8) * Dk + k0 + 4]));
        *reinterpret_cast<uint4*>(dst + (size_t)chunk * 4) = u;
    }
}

// ---------------- pre-pass: embeddings -> fragment-ordered TF32 -------------
// inner = (((ks*2+wn)*4+p)*32 + lane)*4 + q  (wn: 1 bit, p: 2 bits)
__global__ void prep_B(const float* __restrict__ emb) {
    const int nt = blockIdx.x, c = blockIdx.y;
    float* dst = g_B + (size_t)(nt * KCH + c) * B_CHUNK;
    const int tid = threadIdx.x;
    #pragma unroll
    for (int i = 0; i < 4; ++i) {
        const int chunk = tid + 256 * i;          // 0..1023
        const int lane = chunk & 31;
        const int p = (chunk >> 5) & 3;
        const int wn = (chunk >> 7) & 1;
        const int ks = chunk >> 8;                // 0..3
        const int g = lane >> 2, t4 = lane & 3;
        const int n0 = nt * TN + wn * 64 + (2 * p) * 8 + g;
        const int k0 = c * 32 + ks * 8 + t4;
        uint4 u = make_uint4(f2tf32(emb[(size_t)n0 * Dk + k0]),
                             f2tf32(emb[(size_t)n0 * Dk + k0 + 4]),
                             f2tf32(emb[(size_t)(n0 + 8) * Dk + k0]),
                             f2tf32(emb[(size_t)(n0 + 8) * Dk + k0 + 4]));
        *reinterpret_cast<uint4*>(dst + (size_t)chunk * 4) = u;
    }
}

// ---------------- main GEMM: no smem, register-double-buffered LDG ----------
__global__ void __launch_bounds__(128, 2)
gemm_main(const float* __restrict__ topic_b,
          const float* __restrict__ shared_b,
          float* __restrict__ out) {
    const int tid = threadIdx.x;
    const int wid = tid >> 5;
    const int lid = tid & 31;
    const int warp_m = wid >> 1;            // 0..1
    const int warp_n = wid & 1;             // 0..1
    const int g = lid >> 2;
    const int t4 = lid & 3;

    // shared-filter tiles scheduled first (they do 32x the stores)
    const int mt = (blockIdx.x == 0) ? Tt : (blockIdx.x - 1);
    const int nt = blockIdx.y;              // 0..127
    const bool is_shared = (mt == Tt);
    const float* bptr = is_shared ? shared_b : (topic_b + (size_t)mt * FT);
    const int n0 = nt * TN;
    const int b_idx = n0 >> 10;
    const int l0 = n0 & (Ll - 1);

    float acc[4][8][4];                     // 128 regs
    #pragma unroll
    for (int mi = 0; mi < 4; ++mi)
        #pragma unroll
        for (int ni = 0; ni < 8; ++ni)
            #pragma unroll
            for (int r = 0; r < 4; ++r) acc[mi][ni][r] = 0.0f;

    // per-step fragment pointers in float4 units:
    //   step stride = 1024 floats = 256 f4; mi/p stride = 128 floats = 32 f4
    const float4* pA = reinterpret_cast<const float4*>(
                           g_A + (size_t)mt * (KCH * A_CHUNK)) + warp_m * 128 + lid;
    const float4* pB = reinterpret_cast<const float4*>(
                           g_B + (size_t)nt * (KCH * B_CHUNK)) + warp_n * 128 + lid;

    float4 abuf[2][4], bbuf[2][4];
    #pragma unroll
    for (int mi = 0; mi < 4; ++mi) abuf[0][mi] = pA[mi * 32];
    #pragma unroll
    for (int p = 0; p < 4; ++p)    bbuf[0][p]  = pB[p * 32];
    pA += 256; pB += 256;

    #pragma unroll 4
    for (int s = 0; s < NSTEP; ++s) {
        const int cur = s & 1, nxt = cur ^ 1;
        // prefetch step s+1 (pad chunk makes tail read in-bounds)
        #pragma unroll
        for (int mi = 0; mi < 4; ++mi) abuf[nxt][mi] = pA[mi * 32];
        #pragma unroll
        for (int p = 0; p < 4; ++p)    bbuf[nxt][p]  = pB[p * 32];
        pA += 256; pB += 256;

        #pragma unroll
        for (int mi = 0; mi < 4; ++mi) {
            const uint32_t* a = reinterpret_cast<const uint32_t*>(&abuf[cur][mi]);
            #pragma unroll
            for (int p = 0; p < 4; ++p) {
                const uint32_t* b = reinterpret_cast<const uint32_t*>(&bbuf[cur][p]);
                mma_tf32(acc[mi][2 * p], a, b);
                mma_tf32(acc[mi][2 * p + 1], a, b + 2);
            }
        }
    }

    // ---------------- epilogue: bias + direct stores ----------------
    if (!is_shared) {
        const size_t base = ((size_t)(mt * Bb + b_idx) * 256) * Ll + l0;
        #pragma unroll
        for (int mi = 0; mi < 4; ++mi) {
            const int m0 = warp_m * 64 + mi * 16 + g;
            const float bia0 = bptr[m0];
            const float bia1 = bptr[m0 + 8];
            #pragma unroll
            for (int ni = 0; ni < 8; ++ni) {
                const int nn = warp_n * 64 + ni * 8 + 2 * t4;
                float2 v0 = make_float2(acc[mi][ni][0] + bia0, acc[mi][ni][1] + bia0);
                float2 v1 = make_float2(acc[mi][ni][2] + bia1, acc[mi][ni][3] + bia1);
                *reinterpret_cast<float2*>(out + base + (size_t)m0 * Ll + nn) = v0;
                *reinterpret_cast<float2*>(out + base + (size_t)(m0 + 8) * Ll + nn) = v1;
            }
        }
    } else {
        #pragma unroll
        for (int mi = 0; mi < 4; ++mi) {
            const int m0 = warp_m * 64 + mi * 16 + g;
            const float bia0 = bptr[m0];
            const float bia1 = bptr[m0 + 8];
            #pragma unroll
            for (int ni = 0; ni < 8; ++ni) {
                const int nn = warp_n * 64 + ni * 8 + 2 * t4;
                float2 v0 = make_float2(acc[mi][ni][0] + bia0, acc[mi][ni][1] + bia0);
                float2 v1 = make_float2(acc[mi][ni][2] + bia1, acc[mi][ni][3] + bia1);
                for (int t = 0; t < Tt; ++t) {
                    const size_t base =
                        ((size_t)(t * Bb + b_idx) * 256 + FT) * Ll + l0;
                    *reinterpret_cast<float2*>(out + base + (size_t)m0 * Ll + nn) = v0;
                    *reinterpret_cast<float2*>(out + base + (size_t)(m0 + 8) * Ll + nn) = v1;
                }
            }
        }
    }
}

// ---------------- launch ----------------
extern "C" void kernel_launch(void* const* d_in, const int* in_sizes, int n_in,
                              void* d_out, int out_size) {
    const float* emb      = (const float*)d_in[0];
    const float* topic_w  = (const float*)d_in[1];
    const float* topic_b  = (const float*)d_in[2];
    const float* shared_w = (const float*)d_in[3];
    const float* shared_b = (const float*)d_in[4];
    float* out            = (float*)d_out;

    prep_A<<<dim3(MT, KCH), 256>>>(topic_w, shared_w);
    prep_B<<<dim3(NT, KCH), 256>>>(emb);
    gemm_main<<<dim3(MT, NT), 128>>>(topic_b, shared_b, out);
}